// round 16
// baseline (speedup 1.0000x reference)
#include <cuda_runtime.h>
#include <cuda_fp16.h>
#include <mma.h>
#include <cstdint>

using namespace nvcuda;

// Problem constants (fixed by the reference)
#define NMAX 100000
#define EMAX 1250000
#define HDIM 64
#define NCLS 10
#define SCAN_CHUNK 1024
#define MAXBLK 128   // ceil(NMAX/SCAN_CHUNK) = 98 <= 128

// Scratch: __device__ globals (allocation APIs are forbidden).
// fp16 storage end-to-end; fp32 accumulation inside kernels.
__device__ __align__(128) __half g_t2h[NMAX * HDIM];  // messages
__device__ __align__(128) __half g_hh [NMAX * HDIM];  // layer output
__device__ float g_dinv[NMAX];
__device__ int   g_cnt[NMAX];
__device__ int   g_rowptr[NMAX + 1];
__device__ int   g_eidx[EMAX];
__device__ int   g_bsum[MAXBLK];
__device__ int   g_boff[MAXBLK];

// ---------------------------------------------------------------------------
__global__ void k_zerocnt(int n) {
    int i = blockIdx.x * blockDim.x + threadIdx.x;
    if (i < n) g_cnt[i] = 0;
}

__global__ void k_hist(const int* __restrict__ ei, int e, int n) {
    int idx = blockIdx.x * blockDim.x + threadIdx.x;
    if (idx < e) {
        int d = ei[e + idx];
        if (d >= 0 && d < n) atomicAdd(&g_cnt[d], 1);
    }
}

// ---------------------------------------------------------------------------
// Scan phase 1 (per-block sums) FUSED with dinv computation.
__global__ void k_blocksum(int n) {
    const int t = threadIdx.x;
    const int base = blockIdx.x * SCAN_CHUNK + t * 4;
    int s = 0;
#pragma unroll
    for (int j = 0; j < 4; j++) {
        int i = base + j;
        if (i < n) {
            int c = g_cnt[i];
            s += c;
            g_dinv[i] = rsqrtf((float)(c + 1));   // deg incl. self loop
        }
    }
#pragma unroll
    for (int off = 16; off > 0; off >>= 1)
        s += __shfl_down_sync(0xffffffffu, s, off);
    __shared__ int wsum[8];
    if ((t & 31) == 0) wsum[t >> 5] = s;
    __syncthreads();
    if (t == 0) {
        int tot = 0;
#pragma unroll
        for (int w = 0; w < 8; w++) tot += wsum[w];
        g_bsum[blockIdx.x] = tot;
    }
}

__global__ void k_scanb(int nb, int n) {
    const int t = threadIdx.x;       // 128 threads
    int v = (t < nb) ? g_bsum[t] : 0;
    int own = v;
    int lane = t & 31, w = t >> 5;
#pragma unroll
    for (int off = 1; off < 32; off <<= 1) {
        int u = __shfl_up_sync(0xffffffffu, v, off);
        if (lane >= off) v += u;
    }
    __shared__ int wtot[4], woff[4];
    if (lane == 31) wtot[w] = v;
    __syncthreads();
    if (t == 0) {
        int run = 0;
#pragma unroll
        for (int i = 0; i < 4; i++) { woff[i] = run; run += wtot[i]; }
        g_rowptr[n] = run;           // total edge count
    }
    __syncthreads();
    int incl = v + woff[w];
    if (t < nb) g_boff[t] = incl - own;   // exclusive
}

__global__ void k_rowptr(int n) {
    const int t = threadIdx.x;       // 256 threads
    const int base = blockIdx.x * SCAN_CHUNK + t * 4;
    int c[4];
    int s = 0;
#pragma unroll
    for (int j = 0; j < 4; j++) {
        int i = base + j;
        c[j] = (i < n) ? g_cnt[i] : 0;
        s += c[j];
    }
    int v = s, own = s;
    int lane = t & 31, w = t >> 5;
#pragma unroll
    for (int off = 1; off < 32; off <<= 1) {
        int u = __shfl_up_sync(0xffffffffu, v, off);
        if (lane >= off) v += u;
    }
    __shared__ int wtot[8], woff[8];
    if (lane == 31) wtot[w] = v;
    __syncthreads();
    if (t == 0) {
        int run = 0;
#pragma unroll
        for (int i = 0; i < 8; i++) { woff[i] = run; run += wtot[i]; }
    }
    __syncthreads();
    int excl = (v - own) + woff[w] + g_boff[blockIdx.x];
#pragma unroll
    for (int j = 0; j < 4; j++) {
        int i = base + j;
        if (i < n) {
            g_rowptr[i] = excl;
            excl += c[j];
            g_cnt[i] = 0;            // reset fill cursor
        }
    }
}

__global__ void k_fill(const int* __restrict__ ei, int e, int n) {
    int idx = blockIdx.x * blockDim.x + threadIdx.x;
    if (idx < e) {
        int s = ei[idx];
        int d = ei[e + idx];
        if (s >= 0 && s < n && d >= 0 && d < n) {
            int pos = g_rowptr[d] + atomicAdd(&g_cnt[d], 1);
            if (pos < EMAX) g_eidx[pos] = s;
        }
    }
}

// ---------------------------------------------------------------------------
// Tensor-core GEMM: t2h = fp16( (scale? dinv:1) ⊙ ((relu?)hin @ W) ).
// BM=128 rows/block, 256 threads = 8 warps; warp w -> rows [16w,16w+16).
// Layer 1 reads fp32 x, scale=0 (no dinv dependency -> can overlap CSR build).
// Layers 2/3 read fp16 g_hh (relu fused, __hmax2), scale=1.
#define HLD 72                      // fp16 smem row stride (pad vs conflicts)
__global__ void __launch_bounds__(256) k_matmul(
        const float* __restrict__ xin, int use_x,
        const float* __restrict__ W, int n, int relu, int scale) {
    __shared__ __align__(32) char smem[32768];   // 32 KB, aliased
    __half (*Hsh)[HLD] = (__half(*)[HLD])smem;                   // 128x72 fp16
    __half (*Wsh)[HLD] = (__half(*)[HLD])(smem + 128 * HLD * 2); // 64x72 fp16
    float* Osh = (float*)smem;                                   // 8x(16x64) fp32

    const int tid = threadIdx.x;
    const int r0  = blockIdx.x * 128;
    const int lane = tid & 31;
    const int w    = tid >> 5;      // warp 0..7

    // Load W (64x64 fp32 -> fp16): 1024 float4 slots / 256 threads = 4 iters
#pragma unroll
    for (int i = 0; i < 4; i++) {
        int idx = tid + 256 * i;     // 0..1023
        int row = idx >> 4;
        int c4  = idx & 15;
        float4 v = *(const float4*)(W + row * 64 + c4 * 4);
        __half* p = &Wsh[row][c4 * 4];
        p[0] = __float2half_rn(v.x); p[1] = __float2half_rn(v.y);
        p[2] = __float2half_rn(v.z); p[3] = __float2half_rn(v.w);
    }

    // Load H tile (128 rows x 64 cols)
    if (use_x) {
        // fp32 input, convert (no relu on raw features)
#pragma unroll
        for (int i = 0; i < 8; i++) {
            int idx = tid + 256 * i;     // 0..2047 float4 slots
            int row = idx >> 4;
            int c4  = idx & 15;
            int gr  = r0 + row;
            float4 v = make_float4(0.f, 0.f, 0.f, 0.f);
            if (gr < n) v = *(const float4*)(xin + (size_t)gr * 64 + c4 * 4);
            __half* p = &Hsh[row][c4 * 4];
            p[0] = __float2half_rn(v.x); p[1] = __float2half_rn(v.y);
            p[2] = __float2half_rn(v.z); p[3] = __float2half_rn(v.w);
        }
    } else {
        // fp16 input straight from g_hh, fused relu
        const __half2 z2 = __float2half2_rn(0.f);
#pragma unroll
        for (int i = 0; i < 4; i++) {
            int idx = tid + 256 * i;     // 0..1023 uint4 slots (8 halves each)
            int row = idx >> 3;
            int c8  = idx & 7;
            int gr  = r0 + row;
            uint4 v = make_uint4(0u, 0u, 0u, 0u);
            if (gr < n) v = *(const uint4*)(g_hh + (size_t)gr * 64 + c8 * 8);
            if (relu) {
                __half2* h2 = (__half2*)&v;
                h2[0] = __hmax2(h2[0], z2);
                h2[1] = __hmax2(h2[1], z2);
                h2[2] = __hmax2(h2[2], z2);
                h2[3] = __hmax2(h2[3], z2);
            }
            *(uint4*)&Hsh[row][c8 * 8] = v;
        }
    }
    __syncthreads();

    // MMA: warp w -> rows [16w, 16w+16)
    wmma::fragment<wmma::accumulator, 16, 16, 16, float> c[4];
#pragma unroll
    for (int j = 0; j < 4; j++) wmma::fill_fragment(c[j], 0.0f);

#pragma unroll
    for (int k = 0; k < 4; k++) {
        wmma::fragment<wmma::matrix_a, 16, 16, 16, __half, wmma::row_major> a;
        wmma::load_matrix_sync(a, &Hsh[w * 16][k * 16], HLD);
#pragma unroll
        for (int j = 0; j < 4; j++) {
            wmma::fragment<wmma::matrix_b, 16, 16, 16, __half, wmma::row_major> b;
            wmma::load_matrix_sync(b, &Wsh[k * 16][j * 16], HLD);
            wmma::mma_sync(c[j], a, b, c[j]);
        }
    }

    // Frags in registers; reuse smem as fp32 staging.
    __syncthreads();
    float* stage = Osh + w * (16 * 64);          // this warp's 16x64 strip
#pragma unroll
    for (int j = 0; j < 4; j++)
        wmma::store_matrix_sync(stage + j * 16, c[j], 64, wmma::mem_row_major);
    __syncwarp();

    // Epilogue: optional dinv prescale, write fp16 t2h only
#pragma unroll
    for (int it = 0; it < 8; it++) {
        int slot = lane + it * 32;               // 0..255 float4 slots
        int row  = slot >> 4;                    // 0..15
        int c4   = slot & 15;
        int grow = r0 + w * 16 + row;
        if (grow < n) {
            float di = scale ? g_dinv[grow] : 1.0f;
            float4 v = *(float4*)(stage + row * 64 + c4 * 4);
            __half2 p0 = __floats2half2_rn(v.x * di, v.y * di);
            __half2 p1 = __floats2half2_rn(v.z * di, v.w * di);
            uint2 hp;
            hp.x = *(const unsigned int*)&p0;
            hp.y = *(const unsigned int*)&p1;
            *(uint2*)(g_t2h + (size_t)grow * 64 + c4 * 4) = hp;
        }
    }
}

// ---------------------------------------------------------------------------
// Gather: h[i] = fp16( dinv[i]*( m(i) + sum_{e: dst=i} m(src_e) ) + b )
// where m(j) = srcScale ? dinv[j]*t2h[j] : t2h[j] (messages prescaled upstream).
// 16 threads per node, 4 halves (8 B) per thread, fp32 accumulation.
__global__ void k_gather(const float* __restrict__ b, int n, int srcScale) {
    int gid = blockIdx.x * blockDim.x + threadIdx.x;
    int node = gid >> 4;
    if (node >= n) return;
    int q = (gid & 15) << 2;                 // half-column base

    const __half* t2h = g_t2h;
    float dself = srcScale ? __ldg(&g_dinv[node]) : 1.0f;

    uint2 rs = *(const uint2*)(t2h + ((size_t)node << 6) + q);
    float2 sa = __half22float2(*(const __half2*)&rs.x);
    float2 sb = __half22float2(*(const __half2*)&rs.y);
    float4 acc = make_float4(dself * sa.x, dself * sa.y,
                             dself * sb.x, dself * sb.y);
    float4 acc2 = make_float4(0.f, 0.f, 0.f, 0.f);

    int k   = g_rowptr[node];
    int end = g_rowptr[node + 1];

    for (; k + 4 <= end; k += 4) {
        int s0 = __ldg(&g_eidx[k]);
        int s1 = __ldg(&g_eidx[k + 1]);
        int s2 = __ldg(&g_eidx[k + 2]);
        int s3 = __ldg(&g_eidx[k + 3]);
        float d0 = 1.f, d1 = 1.f, d2 = 1.f, d3 = 1.f;
        if (srcScale) {
            d0 = __ldg(&g_dinv[s0]); d1 = __ldg(&g_dinv[s1]);
            d2 = __ldg(&g_dinv[s2]); d3 = __ldg(&g_dinv[s3]);
        }
        uint2 r0 = *(const uint2*)(t2h + ((size_t)s0 << 6) + q);
        uint2 r1 = *(const uint2*)(t2h + ((size_t)s1 << 6) + q);
        uint2 r2 = *(const uint2*)(t2h + ((size_t)s2 << 6) + q);
        uint2 r3 = *(const uint2*)(t2h + ((size_t)s3 << 6) + q);
        float2 a0 = __half22float2(*(const __half2*)&r0.x);
        float2 b0 = __half22float2(*(const __half2*)&r0.y);
        float2 a1 = __half22float2(*(const __half2*)&r1.x);
        float2 b1 = __half22float2(*(const __half2*)&r1.y);
        float2 a2 = __half22float2(*(const __half2*)&r2.x);
        float2 b2 = __half22float2(*(const __half2*)&r2.y);
        float2 a3 = __half22float2(*(const __half2*)&r3.x);
        float2 b3 = __half22float2(*(const __half2*)&r3.y);
        acc.x  = fmaf(d0, a0.x, fmaf(d1, a1.x, acc.x));
        acc.y  = fmaf(d0, a0.y, fmaf(d1, a1.y, acc.y));
        acc.z  = fmaf(d0, b0.x, fmaf(d1, b1.x, acc.z));
        acc.w  = fmaf(d0, b0.y, fmaf(d1, b1.y, acc.w));
        acc2.x = fmaf(d2, a2.x, fmaf(d3, a3.x, acc2.x));
        acc2.y = fmaf(d2, a2.y, fmaf(d3, a3.y, acc2.y));
        acc2.z = fmaf(d2, b2.x, fmaf(d3, b3.x, acc2.z));
        acc2.w = fmaf(d2, b2.y, fmaf(d3, b3.y, acc2.w));
    }
    for (; k < end; k++) {
        int s0 = __ldg(&g_eidx[k]);
        float d0 = srcScale ? __ldg(&g_dinv[s0]) : 1.0f;
        uint2 r0 = *(const uint2*)(t2h + ((size_t)s0 << 6) + q);
        float2 a0 = __half22float2(*(const __half2*)&r0.x);
        float2 b0 = __half22float2(*(const __half2*)&r0.y);
        acc.x = fmaf(d0, a0.x, acc.x); acc.y = fmaf(d0, a0.y, acc.y);
        acc.z = fmaf(d0, b0.x, acc.z); acc.w = fmaf(d0, b0.y, acc.w);
    }
    acc.x += acc2.x; acc.y += acc2.y; acc.z += acc2.z; acc.w += acc2.w;

    float di = __ldg(&g_dinv[node]);
    float4 bb = *(const float4*)(b + q);
    __half2 h0 = __floats2half2_rn(fmaf(di, acc.x, bb.x), fmaf(di, acc.y, bb.y));
    __half2 h1 = __floats2half2_rn(fmaf(di, acc.z, bb.z), fmaf(di, acc.w, bb.w));
    uint2 hp;
    hp.x = *(const unsigned int*)&h0;
    hp.y = *(const unsigned int*)&h1;
    *(uint2*)(g_hh + ((size_t)node << 6) + q) = hp;
}

// ---------------------------------------------------------------------------
// Fused mean-pool (batch sorted -> binary search segments) + linear head.
__global__ void k_pool(const int* __restrict__ batch,
                       const float* __restrict__ Wl, const float* __restrict__ bl,
                       float* __restrict__ out, int n) {
    const __half* h = g_hh;
    const int g = blockIdx.x;
    const int t = threadIdx.x;
    const int c = t & 63;
    const int j = t >> 6;

    auto lb = [&](int key) {
        int lo = 0, hi = n;
        while (lo < hi) {
            int mid = (lo + hi) >> 1;
            if (batch[mid] < key) lo = mid + 1; else hi = mid;
        }
        return lo;
    };
    int lo = lb(g);
    int hi = lb(g + 1);
    int cnt = hi - lo;

    float s = 0.f;
    for (int i = lo + j; i < hi; i += 4)
        s += __half2float(h[(size_t)i * 64 + c]);

    __shared__ float red[256];
    red[t] = s;
    __syncthreads();

    __shared__ float pooled[64];
    if (t < 64) {
        float tot = red[t] + red[t + 64] + red[t + 128] + red[t + 192];
        pooled[t] = tot / (float)max(cnt, 1);
    }
    __syncthreads();

    if (t < NCLS) {
        float acc = bl[t];
#pragma unroll
        for (int k = 0; k < 64; k++)
            acc = fmaf(pooled[k], Wl[k * NCLS + t], acc);
        out[g * NCLS + t] = acc;
    }
}

// ---------------------------------------------------------------------------
extern "C" void kernel_launch(void* const* d_in, const int* in_sizes, int n_in,
                              void* d_out, int out_size) {
    // Resolve inputs BY ELEMENT COUNT (robust to metadata ordering).
    const float* x     = nullptr;
    const int*   ei    = nullptr;
    const int*   batch = nullptr;
    const float* W[3] = {nullptr, nullptr, nullptr};
    const float* B[3] = {nullptr, nullptr, nullptr};
    const float* Wl = nullptr;
    const float* bl = nullptr;
    int nW = 0, nB = 0;
    long long eiCount = 0, batchCount = 0;

    for (int i = 0; i < n_in; i++) {
        long long sz = in_sizes[i];
        if (sz == 10)            bl = (const float*)d_in[i];
        else if (sz == 640)      Wl = (const float*)d_in[i];
        else if (sz == HDIM)     { if (nB < 3) B[nB++] = (const float*)d_in[i]; }
        else if (sz == HDIM*HDIM){ if (nW < 3) W[nW++] = (const float*)d_in[i]; }
        else {
            if (sz >= 6000000)       x = (const float*)d_in[i];
            else if (sz >= 2000000)  { ei = (const int*)d_in[i]; eiCount = sz; }
            else                     { batch = (const int*)d_in[i]; batchCount = sz; }
        }
    }

    float* out = (float*)d_out;
    const int n = (int)batchCount;            // N nodes
    const int e = (int)(eiCount / 2);         // E edges
    const int g = out_size / NCLS;            // G graphs

    const int tb = 256;
    const int nb = (n + SCAN_CHUNK - 1) / SCAN_CHUNK;   // scan blocks (98)
    const int mmGrid = (n + 127) / 128;
    const int gaGrid = (n * 16 + tb - 1) / tb;

    // Side stream + events (created once; graph-capture-safe: record/wait
    // events fork/join the side stream into the capture).
    static cudaStream_t s1 = nullptr;
    static cudaEvent_t evFork = nullptr, evMM1 = nullptr;
    if (!s1) {
        cudaStreamCreateWithFlags(&s1, cudaStreamNonBlocking);
        cudaEventCreateWithFlags(&evFork, cudaEventDisableTiming);
        cudaEventCreateWithFlags(&evMM1, cudaEventDisableTiming);
    }

    // Fork: layer-1 matmul (needs only x, W1 -> no CSR/dinv dependency)
    cudaEventRecord(evFork, 0);
    cudaStreamWaitEvent(s1, evFork, 0);
    k_matmul<<<mmGrid, 256, 0, s1>>>(x, 1, W[0], n, 0, /*scale=*/0);
    cudaEventRecord(evMM1, s1);

    // Main stream: CSR build + dinv (overlaps matmul1)
    k_zerocnt <<<(n + tb - 1) / tb, tb>>>(n);
    k_hist    <<<(e + tb - 1) / tb, tb>>>(ei, e, n);
    k_blocksum<<<nb, tb>>>(n);                           // fused dinv
    k_scanb   <<<1, 128>>>(nb, n);
    k_rowptr  <<<nb, tb>>>(n);
    k_fill    <<<(e + tb - 1) / tb, tb>>>(ei, e, n);

    // Join, then the serial chain
    cudaStreamWaitEvent(0, evMM1, 0);
    k_gather  <<<gaGrid, tb>>>(B[0], n, /*srcScale=*/1); // dinv[src] in gather
    k_matmul  <<<mmGrid, 256>>>(nullptr, 0, W[1], n, 1, /*scale=*/1);
    k_gather  <<<gaGrid, tb>>>(B[1], n, /*srcScale=*/0);
    k_matmul  <<<mmGrid, 256>>>(nullptr, 0, W[2], n, 1, /*scale=*/1);
    k_gather  <<<gaGrid, tb>>>(B[2], n, /*srcScale=*/0);
    k_pool    <<<g, tb>>>(batch, Wl, bl, out, n);
}